// round 6
// baseline (speedup 1.0000x reference)
#include <cuda_runtime.h>
#include <cuda_bf16.h>
#include <math.h>
#include <stdint.h>

typedef unsigned long long ull;

// Problem constants
#define N_ 30000
#define D_ 128
#define E_ 240000
#define E2_ (E_ + N_)          // 270000
#define L_ 6
#define NEG_SLOPE 0.2f
#define EPS_ 1e-5f

// -------------------- device scratch --------------------
__device__ float g_h[N_ * D_];
__device__ float g_xg[N_ * D_];
__device__ float g_xl[N_ * D_];
__device__ float g_xr[N_ * D_];

__device__ int    g_deg[N_];
__device__ int    g_cursor[N_];
__device__ int    g_rowptr[N_ + 1];
__device__ int    g_srcs[E2_];
__device__ int    g_scanbuf[30720];
__device__ int    g_bsum[32];

__device__ double g_lnred[12];
__device__ float  g_bnsum[D_];
__device__ float  g_bnsq[D_];

// -------------------- helpers --------------------
__device__ __forceinline__ void fma2(ull& d, ull a, ull b) {
    asm("fma.rn.f32x2 %0, %1, %2, %0;" : "+l"(d) : "l"(a), "l"(b));
}
__device__ __forceinline__ float2 u2f(ull u) {
    float2 f;
    asm("mov.b64 {%0,%1}, %2;" : "=f"(f.x), "=f"(f.y) : "l"(u));
    return f;
}
__device__ __forceinline__ float leaky(float v) { return v > 0.f ? v : NEG_SLOPE * v; }

// -------------------- small kernels --------------------
__global__ void zero_kernel() {
    int i = blockIdx.x * blockDim.x + threadIdx.x;
    if (i < N_) { g_deg[i] = 0; g_cursor[i] = 0; }
    if (i < 12) g_lnred[i] = 0.0;
    if (i < D_) { g_bnsum[i] = 0.f; g_bnsq[i] = 0.f; }
}

__global__ void gather_kernel(const int* __restrict__ x, const float* __restrict__ emb) {
    int i = blockIdx.x * blockDim.x + threadIdx.x;
    if (i >= N_ * 32) return;
    int n = i >> 5, c4 = i & 31;
    ((float4*)g_h)[i] = ((const float4*)(emb + (size_t)x[n] * D_))[c4];
}

__global__ void hist_kernel(const int* __restrict__ ei) {
    int e = blockIdx.x * blockDim.x + threadIdx.x;
    if (e >= E2_) return;
    int d = (e < E_) ? ei[E_ + e] : (e - E_);
    atomicAdd(&g_deg[d], 1);
}

// coalesced 3-phase scan
__global__ void scan1_kernel() {
    __shared__ int sh[1024];
    int t = threadIdx.x, i = blockIdx.x * 1024 + t;
    int v = (i < N_) ? g_deg[i] : 0;
    sh[t] = v;
    __syncthreads();
    for (int o = 1; o < 1024; o <<= 1) {
        int u = (t >= o) ? sh[t - o] : 0;
        __syncthreads();
        sh[t] += u;
        __syncthreads();
    }
    g_scanbuf[i] = sh[t];
    if (t == 1023) g_bsum[blockIdx.x] = sh[1023];
}
__global__ void scan2_kernel() {
    int t = threadIdx.x;
    int orig = (t < 30) ? g_bsum[t] : 0;
    int v = orig;
    for (int o = 1; o < 32; o <<= 1) {
        int u = __shfl_up_sync(0xffffffffu, v, o);
        if (t >= o) v += u;
    }
    if (t < 30) g_bsum[t] = v - orig;   // exclusive block offsets
}
__global__ void scan3_kernel() {
    int t = threadIdx.x, i = blockIdx.x * 1024 + t;
    if (i > N_) return;
    int v = (i < N_) ? g_deg[i] : 0;
    g_rowptr[i] = g_bsum[blockIdx.x] + g_scanbuf[i] - v;
}

__global__ void scatter_kernel(const int* __restrict__ ei) {
    int e = blockIdx.x * blockDim.x + threadIdx.x;
    if (e >= E2_) return;
    int s, d;
    if (e < E_) { s = ei[e]; d = ei[E_ + e]; }
    else        { s = e - E_; d = s; }
    int pos = g_rowptr[d] + atomicAdd(&g_cursor[d], 1);
    g_srcs[pos] = s;
}

// -------------------- f32x2 packed GEMM --------------------
// C[row0..row0+128) = preop(A) @ W + bias,  W row-major [K=128][N=128]
// blockIdx.y picks (WA,biasA,CA) vs (WB,biasB,CB).
// SMEM layout (floats): As(double,splatted float2) 2*4096, Bs 2*2048 = 49152 B
#define GSMEM 49152

template<int PRE>
__global__ __launch_bounds__(256, 2) void gat_gemm(
    const float* __restrict__ A, const float* __restrict__ resid,
    const float* __restrict__ WA, const float* __restrict__ WB,
    const float* __restrict__ biasA, const float* __restrict__ biasB,
    float* __restrict__ CA, float* __restrict__ CB,
    const float* __restrict__ lnG, const float* __restrict__ lnB, int lnslot)
{
    extern __shared__ float sm[];   // [0,8192): As (float2 view), [8192,12288): Bs
    const int tid  = threadIdx.x;
    const int row0 = blockIdx.x * 128;
    const float* W    = blockIdx.y ? WB : WA;
    const float* bias = blockIdx.y ? biasB : biasA;
    float* C          = blockIdx.y ? CB : CA;

    float mu = 0.f, inv = 0.f;
    if (PRE == 1) {
        double s  = g_lnred[lnslot * 2 + 0];
        double sq = g_lnred[lnslot * 2 + 1];
        const double cnt = (double)N_ * (double)D_;
        double m = s / cnt;
        mu  = (float)m;
        inv = (float)(1.0 / sqrt(sq / cnt - m * m + (double)EPS_));
    }

    const int wid = tid >> 5, lane = tid & 31;
    const int wr = (wid >> 2) * 64;   // warp row slab 0/64
    const int wc = (wid & 3) * 32;    // warp col slab
    const int g  = lane >> 2;         // 0..7
    const int c  = lane & 3;          // 0..3

    // staging assignments
    const int ra = tid & 127;         // A row in tile
    const int ks = (tid >> 7) * 8;    // A k-offset (0 or 8)
    const int kb = tid >> 4;          // B k-row 0..15
    const int cb = (tid & 15) * 8;    // B col
    const bool aok = (row0 + ra) < N_;

    ull acc[8][4];
#pragma unroll
    for (int i = 0; i < 8; i++)
#pragma unroll
        for (int j = 0; j < 4; j++) acc[i][j] = 0ull;

    float4 av0, av1, bv0, bv1;

#define LOAD_TILE(K0) do {                                                     \
    int kk = (K0) + ks;                                                        \
    av0 = make_float4(0.f,0.f,0.f,0.f); av1 = av0;                             \
    if (aok) {                                                                 \
        av0 = *(const float4*)(A + (size_t)(row0 + ra) * D_ + kk);             \
        av1 = *(const float4*)(A + (size_t)(row0 + ra) * D_ + kk + 4);         \
    }                                                                          \
    if (PRE == 1) {                                                            \
        float4 g0 = *(const float4*)(lnG + kk), g1 = *(const float4*)(lnG + kk + 4); \
        float4 b0 = *(const float4*)(lnB + kk), b1 = *(const float4*)(lnB + kk + 4); \
        av0.x = fmaxf((av0.x - mu) * inv * g0.x + b0.x, 0.f);                  \
        av0.y = fmaxf((av0.y - mu) * inv * g0.y + b0.y, 0.f);                  \
        av0.z = fmaxf((av0.z - mu) * inv * g0.z + b0.z, 0.f);                  \
        av0.w = fmaxf((av0.w - mu) * inv * g0.w + b0.w, 0.f);                  \
        av1.x = fmaxf((av1.x - mu) * inv * g1.x + b1.x, 0.f);                  \
        av1.y = fmaxf((av1.y - mu) * inv * g1.y + b1.y, 0.f);                  \
        av1.z = fmaxf((av1.z - mu) * inv * g1.z + b1.z, 0.f);                  \
        av1.w = fmaxf((av1.w - mu) * inv * g1.w + b1.w, 0.f);                  \
    } else if (PRE == 2) {                                                     \
        if (aok) {                                                             \
            float4 r0 = *(const float4*)(resid + (size_t)(row0 + ra) * D_ + kk);     \
            float4 r1 = *(const float4*)(resid + (size_t)(row0 + ra) * D_ + kk + 4); \
            av0.x += r0.x; av0.y += r0.y; av0.z += r0.z; av0.w += r0.w;        \
            av1.x += r1.x; av1.y += r1.y; av1.z += r1.z; av1.w += r1.w;        \
        }                                                                      \
    }                                                                          \
    bv0 = *(const float4*)(W + (size_t)((K0) + kb) * D_ + cb);                 \
    bv1 = *(const float4*)(W + (size_t)((K0) + kb) * D_ + cb + 4);             \
} while (0)

#define STORE_TILE(B) do {                                                     \
    float2* asd = (float2*)sm + (B) * 2048;                                    \
    asd[(ks + 0) * 128 + ra] = make_float2(av0.x, av0.x);                      \
    asd[(ks + 1) * 128 + ra] = make_float2(av0.y, av0.y);                      \
    asd[(ks + 2) * 128 + ra] = make_float2(av0.z, av0.z);                      \
    asd[(ks + 3) * 128 + ra] = make_float2(av0.w, av0.w);                      \
    asd[(ks + 4) * 128 + ra] = make_float2(av1.x, av1.x);                      \
    asd[(ks + 5) * 128 + ra] = make_float2(av1.y, av1.y);                      \
    asd[(ks + 6) * 128 + ra] = make_float2(av1.z, av1.z);                      \
    asd[(ks + 7) * 128 + ra] = make_float2(av1.w, av1.w);                      \
    float* bsd = sm + 8192 + (B) * 2048;                                       \
    *(float4*)(bsd + kb * 128 + cb)     = bv0;                                 \
    *(float4*)(bsd + kb * 128 + cb + 4) = bv1;                                 \
} while (0)

    LOAD_TILE(0);
    STORE_TILE(0);
    __syncthreads();

#pragma unroll
    for (int t = 0; t < 8; t++) {
        if (t < 7) LOAD_TILE((t + 1) * 16);

        const ull*   as = (const ull*)sm + (t & 1) * 2048;
        const float* bs = sm + 8192 + (t & 1) * 2048;
#pragma unroll
        for (int k = 0; k < 16; k++) {
            ull a[8];
#pragma unroll
            for (int i = 0; i < 8; i++)
                a[i] = as[k * 128 + wr + g + 8 * i];
            ulonglong2 t0 = *(const ulonglong2*)(bs + k * 128 + wc + c * 8);
            ulonglong2 t1 = *(const ulonglong2*)(bs + k * 128 + wc + c * 8 + 4);
#pragma unroll
            for (int i = 0; i < 8; i++) {
                fma2(acc[i][0], a[i], t0.x);
                fma2(acc[i][1], a[i], t0.y);
                fma2(acc[i][2], a[i], t1.x);
                fma2(acc[i][3], a[i], t1.y);
            }
        }

        if (t < 7) {
            STORE_TILE((t + 1) & 1);
            __syncthreads();
        }
    }

    // epilogue
    {
        int col = wc + c * 8;
        float4 b0 = *(const float4*)(bias + col);
        float4 b1 = *(const float4*)(bias + col + 4);
#pragma unroll
        for (int i = 0; i < 8; i++) {
            int row = row0 + wr + g + 8 * i;
            if (row < N_) {
                float2 p0 = u2f(acc[i][0]), p1 = u2f(acc[i][1]);
                float2 p2 = u2f(acc[i][2]), p3 = u2f(acc[i][3]);
                float4 o0 = make_float4(p0.x + b0.x, p0.y + b0.y, p1.x + b0.z, p1.y + b0.w);
                float4 o1 = make_float4(p2.x + b1.x, p2.y + b1.y, p3.x + b1.z, p3.y + b1.w);
                *(float4*)(C + (size_t)row * D_ + col)     = o0;
                *(float4*)(C + (size_t)row * D_ + col + 4) = o1;
            }
        }
    }
#undef LOAD_TILE
#undef STORE_TILE
}

// -------------------- aggregation (warp per dst) + fused LN stats ----------
template<int STATS>
__global__ __launch_bounds__(256) void agg_kernel(
    const float* __restrict__ att, const float* __restrict__ cbias, int slot)
{
    __shared__ float ssum[8], ssq[8];
    int tid = threadIdx.x;
    int warp = (blockIdx.x * blockDim.x + tid) >> 5;
    int lane = tid & 31;
    int wid = tid >> 5;

    float4 o = make_float4(0.f, 0.f, 0.f, 0.f);
    if (warp < N_) {
        const float4 attv = ((const float4*)att)[lane];
        const float4 xrv  = ((const float4*)(g_xr + (size_t)warp * D_))[lane];
        int beg = g_rowptr[warp], end = g_rowptr[warp + 1];

        float m = -INFINITY, lsum = 0.f;
        float4 acc = make_float4(0.f, 0.f, 0.f, 0.f);
        for (int e = beg; e < end; e++) {
            int s = g_srcs[e];
            float4 v = ((const float4*)(g_xl + (size_t)s * D_))[lane];
            float p = leaky(v.x + xrv.x) * attv.x
                    + leaky(v.y + xrv.y) * attv.y
                    + leaky(v.z + xrv.z) * attv.z
                    + leaky(v.w + xrv.w) * attv.w;
#pragma unroll
            for (int of = 16; of > 0; of >>= 1)
                p += __shfl_xor_sync(0xffffffffu, p, of);
            float mn    = fmaxf(m, p);
            float scale = __expf(m - mn);
            float w     = __expf(p - mn);
            acc.x = acc.x * scale + w * v.x;
            acc.y = acc.y * scale + w * v.y;
            acc.z = acc.z * scale + w * v.z;
            acc.w = acc.w * scale + w * v.w;
            lsum  = lsum * scale + w;
            m = mn;
        }
        float invl = 1.f / lsum;
        float4 cb = ((const float4*)cbias)[lane];
        o = make_float4(acc.x * invl + cb.x, acc.y * invl + cb.y,
                        acc.z * invl + cb.z, acc.w * invl + cb.w);
        ((float4*)(g_xg + (size_t)warp * D_))[lane] = o;
    }

    if (STATS) {
        float s = o.x + o.y + o.z + o.w;
        float q = o.x * o.x + o.y * o.y + o.z * o.z + o.w * o.w;
#pragma unroll
        for (int of = 16; of > 0; of >>= 1) {
            s += __shfl_xor_sync(0xffffffffu, s, of);
            q += __shfl_xor_sync(0xffffffffu, q, of);
        }
        if (lane == 0) { ssum[wid] = s; ssq[wid] = q; }
        __syncthreads();
        if (tid == 0) {
            double S = 0.0, Q = 0.0;
#pragma unroll
            for (int i = 0; i < 8; i++) { S += (double)ssum[i]; Q += (double)ssq[i]; }
            atomicAdd(&g_lnred[slot * 2 + 0], S);
            atomicAdd(&g_lnred[slot * 2 + 1], Q);
        }
    }
}

// -------------------- BatchNorm --------------------
__global__ void bnstats_kernel(const float* __restrict__ out) {
    int c = threadIdx.x;
    float s = 0.f, q = 0.f;
    for (int r = blockIdx.x; r < N_; r += gridDim.x) {
        float v = out[(size_t)r * D_ + c];
        s += v; q += v * v;
    }
    atomicAdd(&g_bnsum[c], s);
    atomicAdd(&g_bnsq[c], q);
}

__global__ void bnnorm_kernel(float* __restrict__ out,
                              const float* __restrict__ bng,
                              const float* __restrict__ bnb) {
    int i = blockIdx.x * blockDim.x + threadIdx.x;
    if (i >= N_ * 32) return;
    int c4 = i & 31;
    float4 v  = ((float4*)out)[i];
    float4 su = ((const float4*)g_bnsum)[c4];
    float4 qu = ((const float4*)g_bnsq)[c4];
    float4 g  = ((const float4*)bng)[c4];
    float4 b  = ((const float4*)bnb)[c4];
    const float invN = 1.f / (float)N_;
    float mu, var;
    mu = su.x * invN; var = qu.x * invN - mu * mu;
    v.x = (v.x - mu) * rsqrtf(var + EPS_) * g.x + b.x;
    mu = su.y * invN; var = qu.y * invN - mu * mu;
    v.y = (v.y - mu) * rsqrtf(var + EPS_) * g.y + b.y;
    mu = su.z * invN; var = qu.z * invN - mu * mu;
    v.z = (v.z - mu) * rsqrtf(var + EPS_) * g.z + b.z;
    mu = su.w * invN; var = qu.w * invN - mu * mu;
    v.w = (v.w - mu) * rsqrtf(var + EPS_) * g.w + b.w;
    ((float4*)out)[i] = v;
}

// -------------------- launch --------------------
extern "C" void kernel_launch(void* const* d_in, const int* in_sizes, int n_in,
                              void* d_out, int out_size) {
    const int*   x    = (const int*)d_in[0];
    const int*   ei   = (const int*)d_in[1];
    const float* emb  = (const float*)d_in[2];
    const float* Wl   = (const float*)d_in[3];
    const float* bl   = (const float*)d_in[4];
    const float* Wr   = (const float*)d_in[5];
    const float* br   = (const float*)d_in[6];
    const float* att  = (const float*)d_in[7];
    const float* cb   = (const float*)d_in[8];
    const float* lng  = (const float*)d_in[9];
    const float* lnb  = (const float*)d_in[10];
    const float* linW = (const float*)d_in[11];
    const float* linb = (const float*)d_in[12];
    const float* bng  = (const float*)d_in[13];
    const float* bnb  = (const float*)d_in[14];
    float* out = (float*)d_out;

    float *p_h, *p_xg, *p_xl, *p_xr;
    cudaGetSymbolAddress((void**)&p_h,  g_h);
    cudaGetSymbolAddress((void**)&p_xg, g_xg);
    cudaGetSymbolAddress((void**)&p_xl, g_xl);
    cudaGetSymbolAddress((void**)&p_xr, g_xr);

    cudaFuncSetAttribute(gat_gemm<0>, cudaFuncAttributeMaxDynamicSharedMemorySize, GSMEM);
    cudaFuncSetAttribute(gat_gemm<1>, cudaFuncAttributeMaxDynamicSharedMemorySize, GSMEM);
    cudaFuncSetAttribute(gat_gemm<2>, cudaFuncAttributeMaxDynamicSharedMemorySize, GSMEM);

    const int TPB = 256;
    zero_kernel<<<(N_ + TPB - 1) / TPB, TPB>>>();
    gather_kernel<<<(N_ * 32 + TPB - 1) / TPB, TPB>>>(x, emb);
    hist_kernel<<<(E2_ + TPB - 1) / TPB, TPB>>>(ei);
    scan1_kernel<<<30, 1024>>>();
    scan2_kernel<<<1, 32>>>();
    scan3_kernel<<<30, 1024>>>();
    scatter_kernel<<<(E2_ + TPB - 1) / TPB, TPB>>>(ei);

    const int NTILE = (N_ + 127) / 128;              // 235
    const dim3 GRID2(NTILE, 2), GRID1(NTILE, 1);
    const int AGG_GRID  = (N_ * 32 + TPB - 1) / TPB; // warp per node

    for (int i = 0; i < L_; i++) {
        const float* Ain = (i == 0) ? p_h : p_xg;
        const float* WL = Wl + (size_t)i * 16384;
        const float* WR = Wr + (size_t)i * 16384;
        if (i == 0) {
            gat_gemm<0><<<GRID2, 256, GSMEM>>>(
                Ain, nullptr, WL, WR, bl + i * D_, br + i * D_,
                p_xl, p_xr, nullptr, nullptr, 0);
        } else {
            gat_gemm<1><<<GRID2, 256, GSMEM>>>(
                Ain, nullptr, WL, WR, bl + i * D_, br + i * D_,
                p_xl, p_xr, lng + (i - 1) * D_, lnb + (i - 1) * D_, i - 1);
        }
        if (i < L_ - 1)
            agg_kernel<1><<<AGG_GRID, 256>>>(att + i * D_, cb + i * D_, i);
        else
            agg_kernel<0><<<AGG_GRID, 256>>>(att + i * D_, cb + i * D_, 0);
    }

    gat_gemm<2><<<GRID1, 256, GSMEM>>>(
        p_xg, p_h, linW, nullptr, linb, nullptr,
        out, nullptr, nullptr, nullptr, 0);
    bnstats_kernel<<<256, D_>>>(out);
    bnnorm_kernel<<<(N_ * 32 + TPB - 1) / TPB, TPB>>>(out, bng, bnb);
}

// round 7
// speedup vs baseline: 1.3027x; 1.3027x over previous
#include <cuda_runtime.h>
#include <cuda_bf16.h>
#include <math.h>
#include <stdint.h>

// Problem constants
#define N_ 30000
#define D_ 128
#define E_ 240000
#define E2_ (E_ + N_)          // 270000
#define L_ 6
#define NEG_SLOPE 0.2f
#define EPS_ 1e-5f

// -------------------- device scratch --------------------
__device__ float g_h[N_ * D_];
__device__ float g_xg[N_ * D_];
__device__ float g_xl[N_ * D_];
__device__ float g_xr[N_ * D_];
// packed weights: per matrix [n][k/2] uint (2 bf16 along k), transposed from W[k][n]
__device__ uint32_t g_Wph[13 * 8192];
__device__ uint32_t g_Wpl[13 * 8192];

__device__ int    g_deg[N_];
__device__ int    g_cursor[N_];
__device__ int    g_rowptr[N_ + 1];
__device__ int    g_srcs[E2_];
__device__ int    g_scanbuf[30720];
__device__ int    g_bsum[32];

__device__ double g_lnred[12];
__device__ float  g_bnsum[D_];
__device__ float  g_bnsq[D_];

// -------------------- helpers --------------------
__device__ __forceinline__ void mma_bf16(float* d, const uint32_t* a, const uint32_t* b) {
    asm volatile(
        "mma.sync.aligned.m16n8k16.row.col.f32.bf16.bf16.f32 "
        "{%0,%1,%2,%3}, {%4,%5,%6,%7}, {%8,%9}, {%0,%1,%2,%3};"
        : "+f"(d[0]), "+f"(d[1]), "+f"(d[2]), "+f"(d[3])
        : "r"(a[0]), "r"(a[1]), "r"(a[2]), "r"(a[3]), "r"(b[0]), "r"(b[1]));
}
// split (x,y) into packed bf16x2 hi word + lo-residual word
__device__ __forceinline__ void split2(float x, float y, uint32_t& hi, uint32_t& lo) {
    __nv_bfloat16 hx = __float2bfloat16(x), hy = __float2bfloat16(y);
    float lx = x - __bfloat162float(hx);
    float ly = y - __bfloat162float(hy);
    __nv_bfloat16 lxh = __float2bfloat16(lx), lyh = __float2bfloat16(ly);
    hi = (uint32_t)__bfloat16_as_ushort(hx) | ((uint32_t)__bfloat16_as_ushort(hy) << 16);
    lo = (uint32_t)__bfloat16_as_ushort(lxh) | ((uint32_t)__bfloat16_as_ushort(lyh) << 16);
}
__device__ __forceinline__ float leaky(float v) { return v > 0.f ? v : NEG_SLOPE * v; }

// -------------------- small kernels --------------------
__global__ void zero_kernel() {
    int i = blockIdx.x * blockDim.x + threadIdx.x;
    if (i < N_) { g_deg[i] = 0; g_cursor[i] = 0; }
    if (i < 12) g_lnred[i] = 0.0;
    if (i < D_) { g_bnsum[i] = 0.f; g_bnsq[i] = 0.f; }
}

__global__ void gather_kernel(const int* __restrict__ x, const float* __restrict__ emb) {
    int i = blockIdx.x * blockDim.x + threadIdx.x;
    if (i >= N_ * 32) return;
    int n = i >> 5, c4 = i & 31;
    ((float4*)g_h)[i] = ((const float4*)(emb + (size_t)x[n] * D_))[c4];
}

__global__ void hist_kernel(const int* __restrict__ ei) {
    int e = blockIdx.x * blockDim.x + threadIdx.x;
    if (e >= E2_) return;
    int d = (e < E_) ? ei[E_ + e] : (e - E_);
    atomicAdd(&g_deg[d], 1);
}

// coalesced 3-phase scan
__global__ void scan1_kernel() {
    __shared__ int sh[1024];
    int t = threadIdx.x, i = blockIdx.x * 1024 + t;
    int v = (i < N_) ? g_deg[i] : 0;
    sh[t] = v;
    __syncthreads();
    for (int o = 1; o < 1024; o <<= 1) {
        int u = (t >= o) ? sh[t - o] : 0;
        __syncthreads();
        sh[t] += u;
        __syncthreads();
    }
    g_scanbuf[i] = sh[t];
    if (t == 1023) g_bsum[blockIdx.x] = sh[1023];
}
__global__ void scan2_kernel() {
    int t = threadIdx.x;
    int orig = (t < 30) ? g_bsum[t] : 0;
    int v = orig;
    for (int o = 1; o < 32; o <<= 1) {
        int u = __shfl_up_sync(0xffffffffu, v, o);
        if (t >= o) v += u;
    }
    if (t < 30) g_bsum[t] = v - orig;   // exclusive block offsets
}
__global__ void scan3_kernel() {
    int t = threadIdx.x, i = blockIdx.x * 1024 + t;
    if (i > N_) return;
    int v = (i < N_) ? g_deg[i] : 0;
    g_rowptr[i] = g_bsum[blockIdx.x] + g_scanbuf[i] - v;
}

__global__ void scatter_kernel(const int* __restrict__ ei) {
    int e = blockIdx.x * blockDim.x + threadIdx.x;
    if (e >= E2_) return;
    int s, d;
    if (e < E_) { s = ei[e]; d = ei[E_ + e]; }
    else        { s = e - E_; d = s; }
    int pos = g_rowptr[d] + atomicAdd(&g_cursor[d], 1);
    g_srcs[pos] = s;
}

// pack weights: W[k][n] fp32 -> [n][k/2] bf16x2 hi/lo, 13 matrices
__global__ void pack_kernel(const float* __restrict__ Wl, const float* __restrict__ Wr,
                            const float* __restrict__ linW) {
    int idx = blockIdx.x * 256 + threadIdx.x;   // over 13*64*128 (w-major, n fastest)
    if (idx >= 13 * 8192) return;
    int mat = idx / 8192;
    int rem = idx - mat * 8192;
    int w = rem >> 7;        // k-pair 0..63
    int n = rem & 127;
    const float* src = (mat < 6) ? (Wl + mat * 16384)
                     : (mat < 12) ? (Wr + (mat - 6) * 16384) : linW;
    float v0 = src[(2 * w) * D_ + n];
    float v1 = src[(2 * w + 1) * D_ + n];
    uint32_t hi, lo;
    split2(v0, v1, hi, lo);
    g_Wph[mat * 8192 + n * 64 + w] = hi;
    g_Wpl[mat * 8192 + n * 64 + w] = lo;
}

// -------------------- bf16-split mma.sync GEMM --------------------
// C = preop(A)[128-row tile] @ W + bias, full K=128 single stage.
// PRE: 0 identity, 1 LN(graph)+ReLU, 2 A+resid.  NB: 1 or 2 weight matrices.
#define PW 68                       // uints per row (bank-conflict-free: 4-stride)
#define TILEU (128 * PW)            // 8704 uints per array
#define SMEM_NB1 (4 * TILEU * 4)    // 139264 B
#define SMEM_NB2 (6 * TILEU * 4)    // 208896 B

template<int PRE, int NB>
__global__ __launch_bounds__(256, 1) void gat_gemm(
    const float* __restrict__ A, const float* __restrict__ resid,
    const uint32_t* __restrict__ WhA, const uint32_t* __restrict__ WlA,
    const uint32_t* __restrict__ WhB, const uint32_t* __restrict__ WlB,
    const float* __restrict__ biasA, const float* __restrict__ biasB,
    float* __restrict__ CA, float* __restrict__ CB,
    const float* __restrict__ lnG, const float* __restrict__ lnB, int lnslot)
{
    extern __shared__ uint32_t smu[];
    uint32_t* Ah  = smu;
    uint32_t* Al  = smu + TILEU;
    uint32_t* B0h = smu + 2 * TILEU;
    uint32_t* B0l = smu + 3 * TILEU;
    uint32_t* B1h = smu + 4 * TILEU;
    uint32_t* B1l = smu + 5 * TILEU;

    const int tid = threadIdx.x, wid = tid >> 5, lane = tid & 31;
    const int row0 = blockIdx.x * 128;

    float mu = 0.f, inv = 0.f;
    if (PRE == 1) {
        double s  = g_lnred[lnslot * 2 + 0];
        double sq = g_lnred[lnslot * 2 + 1];
        const double cnt = (double)N_ * (double)D_;
        double m = s / cnt;
        mu  = (float)m;
        inv = (float)(1.0 / sqrt(sq / cnt - m * m + (double)EPS_));
    }

    // ---- stage A (pre-op + bf16 split, packed pairs) ----
    {
        const int r = tid & 127, half = tid >> 7;
        const bool aok = (row0 + r) < N_;
        const float* Arow = A + (size_t)(row0 + r) * D_;
        const float* Rrow = (PRE == 2) ? (resid + (size_t)(row0 + r) * D_) : nullptr;
#pragma unroll 4
        for (int i = 0; i < 16; i++) {
            int c4 = half * 16 + i;           // float4 index 0..31
            float4 v = make_float4(0.f, 0.f, 0.f, 0.f);
            if (aok) v = *(const float4*)(Arow + c4 * 4);
            if (PRE == 1) {
                float4 lg = *(const float4*)(lnG + c4 * 4);
                float4 lb = *(const float4*)(lnB + c4 * 4);
                v.x = fmaxf((v.x - mu) * inv * lg.x + lb.x, 0.f);
                v.y = fmaxf((v.y - mu) * inv * lg.y + lb.y, 0.f);
                v.z = fmaxf((v.z - mu) * inv * lg.z + lb.z, 0.f);
                v.w = fmaxf((v.w - mu) * inv * lg.w + lb.w, 0.f);
            } else if (PRE == 2) {
                if (aok) {
                    float4 rv = *(const float4*)(Rrow + c4 * 4);
                    v.x += rv.x; v.y += rv.y; v.z += rv.z; v.w += rv.w;
                }
            }
            uint32_t h0, l0, h1, l1;
            split2(v.x, v.y, h0, l0);
            split2(v.z, v.w, h1, l1);
            *(uint2*)&Ah[r * PW + c4 * 2] = make_uint2(h0, h1);
            *(uint2*)&Al[r * PW + c4 * 2] = make_uint2(l0, l1);
        }
        // ---- stage B (pre-packed in global, row-copy) ----
#pragma unroll 2
        for (int i = 0; i < 8; i++) {
            int w4 = half * 8 + i;            // uint4 index 0..15 (64 words/row)
            *(uint4*)&B0h[r * PW + w4 * 4] = *(const uint4*)(WhA + r * 64 + w4 * 4);
            *(uint4*)&B0l[r * PW + w4 * 4] = *(const uint4*)(WlA + r * 64 + w4 * 4);
            if (NB == 2) {
                *(uint4*)&B1h[r * PW + w4 * 4] = *(const uint4*)(WhB + r * 64 + w4 * 4);
                *(uint4*)&B1l[r * PW + w4 * 4] = *(const uint4*)(WlB + r * 64 + w4 * 4);
            }
        }
    }
    __syncthreads();

    const int g  = lane >> 2;        // 0..7
    const int tg = lane & 3;         // 0..3
    const int wr = (wid >> 2) * 64;  // warp row slab
    const int wc = (wid & 3) * 32;   // warp col slab

    float acc0[4][4][4], acc1[4][4][4];
#pragma unroll
    for (int mi = 0; mi < 4; mi++)
#pragma unroll
        for (int ni = 0; ni < 4; ni++)
#pragma unroll
            for (int j = 0; j < 4; j++) {
                acc0[mi][ni][j] = 0.f;
                if (NB == 2) acc1[mi][ni][j] = 0.f;
            }

#pragma unroll 2
    for (int ks = 0; ks < 8; ks++) {
        const int k0 = ks * 8;       // word offset (16 k-elems = 8 words)
        uint32_t ah[4][4], al[4][4];
#pragma unroll
        for (int mi = 0; mi < 4; mi++) {
            int o1 = (wr + mi * 16 + g) * PW + k0 + tg;
            int o2 = o1 + 8 * PW;
            ah[mi][0] = Ah[o1]; ah[mi][1] = Ah[o2];
            ah[mi][2] = Ah[o1 + 4]; ah[mi][3] = Ah[o2 + 4];
            al[mi][0] = Al[o1]; al[mi][1] = Al[o2];
            al[mi][2] = Al[o1 + 4]; al[mi][3] = Al[o2 + 4];
        }
        {
            uint32_t bh[4][2], bl[4][2];
#pragma unroll
            for (int ni = 0; ni < 4; ni++) {
                int o = (wc + ni * 8 + g) * PW + k0 + tg;
                bh[ni][0] = B0h[o]; bh[ni][1] = B0h[o + 4];
                bl[ni][0] = B0l[o]; bl[ni][1] = B0l[o + 4];
            }
#pragma unroll
            for (int mi = 0; mi < 4; mi++)
#pragma unroll
                for (int ni = 0; ni < 4; ni++)
                    mma_bf16(acc0[mi][ni], ah[mi], bh[ni]);
#pragma unroll
            for (int mi = 0; mi < 4; mi++)
#pragma unroll
                for (int ni = 0; ni < 4; ni++)
                    mma_bf16(acc0[mi][ni], ah[mi], bl[ni]);
#pragma unroll
            for (int mi = 0; mi < 4; mi++)
#pragma unroll
                for (int ni = 0; ni < 4; ni++)
                    mma_bf16(acc0[mi][ni], al[mi], bh[ni]);
        }
        if (NB == 2) {
            uint32_t bh[4][2], bl[4][2];
#pragma unroll
            for (int ni = 0; ni < 4; ni++) {
                int o = (wc + ni * 8 + g) * PW + k0 + tg;
                bh[ni][0] = B1h[o]; bh[ni][1] = B1h[o + 4];
                bl[ni][0] = B1l[o]; bl[ni][1] = B1l[o + 4];
            }
#pragma unroll
            for (int mi = 0; mi < 4; mi++)
#pragma unroll
                for (int ni = 0; ni < 4; ni++)
                    mma_bf16(acc1[mi][ni], ah[mi], bh[ni]);
#pragma unroll
            for (int mi = 0; mi < 4; mi++)
#pragma unroll
                for (int ni = 0; ni < 4; ni++)
                    mma_bf16(acc1[mi][ni], ah[mi], bl[ni]);
#pragma unroll
            for (int mi = 0; mi < 4; mi++)
#pragma unroll
                for (int ni = 0; ni < 4; ni++)
                    mma_bf16(acc1[mi][ni], al[mi], bh[ni]);
        }
    }

    // ---- epilogue ----
#pragma unroll
    for (int mat = 0; mat < NB; mat++) {
        const float* bias = mat ? biasB : biasA;
        float* C          = mat ? CB : CA;
#pragma unroll
        for (int mi = 0; mi < 4; mi++) {
            int r1 = row0 + wr + mi * 16 + g;
            int r2 = r1 + 8;
#pragma unroll
            for (int ni = 0; ni < 4; ni++) {
                float* a = mat ? acc1[mi][ni] : acc0[mi][ni];
                int col = wc + ni * 8 + tg * 2;
                float2 bv = *(const float2*)(bias + col);
                if (r1 < N_) {
                    float2 o = make_float2(a[0] + bv.x, a[1] + bv.y);
                    *(float2*)(C + (size_t)r1 * D_ + col) = o;
                }
                if (r2 < N_) {
                    float2 o = make_float2(a[2] + bv.x, a[3] + bv.y);
                    *(float2*)(C + (size_t)r2 * D_ + col) = o;
                }
            }
        }
    }
}

// -------------------- aggregation (warp per dst) + fused LN stats ----------
template<int STATS>
__global__ __launch_bounds__(256) void agg_kernel(
    const float* __restrict__ att, const float* __restrict__ cbias, int slot)
{
    __shared__ float ssum[8], ssq[8];
    int tid = threadIdx.x;
    int warp = (blockIdx.x * blockDim.x + tid) >> 5;
    int lane = tid & 31;
    int wid = tid >> 5;

    float4 o = make_float4(0.f, 0.f, 0.f, 0.f);
    if (warp < N_) {
        const float4 attv = ((const float4*)att)[lane];
        const float4 xrv  = ((const float4*)(g_xr + (size_t)warp * D_))[lane];
        int beg = g_rowptr[warp], end = g_rowptr[warp + 1];

        float m = -INFINITY, lsum = 0.f;
        float4 acc = make_float4(0.f, 0.f, 0.f, 0.f);
        for (int e = beg; e < end; e++) {
            int s = g_srcs[e];
            float4 v = ((const float4*)(g_xl + (size_t)s * D_))[lane];
            float p = leaky(v.x + xrv.x) * attv.x
                    + leaky(v.y + xrv.y) * attv.y
                    + leaky(v.z + xrv.z) * attv.z
                    + leaky(v.w + xrv.w) * attv.w;
#pragma unroll
            for (int of = 16; of > 0; of >>= 1)
                p += __shfl_xor_sync(0xffffffffu, p, of);
            float mn    = fmaxf(m, p);
            float scale = __expf(m - mn);
            float w     = __expf(p - mn);
            acc.x = acc.x * scale + w * v.x;
            acc.y = acc.y * scale + w * v.y;
            acc.z = acc.z * scale + w * v.z;
            acc.w = acc.w * scale + w * v.w;
            lsum  = lsum * scale + w;
            m = mn;
        }
        float invl = 1.f / lsum;
        float4 cb = ((const float4*)cbias)[lane];
        o = make_float4(acc.x * invl + cb.x, acc.y * invl + cb.y,
                        acc.z * invl + cb.z, acc.w * invl + cb.w);
        ((float4*)(g_xg + (size_t)warp * D_))[lane] = o;
    }

    if (STATS) {
        float s = o.x + o.y + o.z + o.w;
        float q = o.x * o.x + o.y * o.y + o.z * o.z + o.w * o.w;
#pragma unroll
        for (int of = 16; of > 0; of >>= 1) {
            s += __shfl_xor_sync(0xffffffffu, s, of);
            q += __shfl_xor_sync(0xffffffffu, q, of);
        }
        if (lane == 0) { ssum[wid] = s; ssq[wid] = q; }
        __syncthreads();
        if (tid == 0) {
            double S = 0.0, Q = 0.0;
#pragma unroll
            for (int i = 0; i < 8; i++) { S += (double)ssum[i]; Q += (double)ssq[i]; }
            atomicAdd(&g_lnred[slot * 2 + 0], S);
            atomicAdd(&g_lnred[slot * 2 + 1], Q);
        }
    }
}

// -------------------- BatchNorm --------------------
__global__ void bnstats_kernel(const float* __restrict__ out) {
    int c = threadIdx.x;
    float s = 0.f, q = 0.f;
    for (int r = blockIdx.x; r < N_; r += gridDim.x) {
        float v = out[(size_t)r * D_ + c];
        s += v; q += v * v;
    }
    atomicAdd(&g_bnsum[c], s);
    atomicAdd(&g_bnsq[c], q);
}

__global__ void bnnorm_kernel(float* __restrict__ out,
                              const float* __restrict__ bng,
                              const float* __restrict__ bnb) {
    int i = blockIdx.x * blockDim.x + threadIdx.x;
    if (i >= N_ * 32) return;
    int c4 = i & 31;
    float4 v  = ((float4*)out)[i];
    float4 su = ((const float4*)g_bnsum)[c4];
    float4 qu = ((const float4*)g_bnsq)[c4];
    float4 g  = ((const float4*)bng)[c4];
    float4 b  = ((const float4*)bnb)[c4];
    const float invN = 1.f / (float)N_;
    float mu, var;
    mu = su.x * invN; var = qu.x * invN - mu * mu;
    v.x = (v.x - mu) * rsqrtf(var + EPS_) * g.x + b.x;
    mu = su.y * invN; var = qu.y * invN - mu * mu;
    v.y = (v.y - mu) * rsqrtf(var + EPS_) * g.y + b.y;
    mu = su.z * invN; var = qu.z * invN - mu * mu;
    v.z = (v.z - mu) * rsqrtf(var + EPS_) * g.z + b.z;
    mu = su.w * invN; var = qu.w * invN - mu * mu;
    v.w = (v.w - mu) * rsqrtf(var + EPS_) * g.w + b.w;
    ((float4*)out)[i] = v;
}

// -------------------- launch --------------------
extern "C" void kernel_launch(void* const* d_in, const int* in_sizes, int n_in,
                              void* d_out, int out_size) {
    const int*   x    = (const int*)d_in[0];
    const int*   ei   = (const int*)d_in[1];
    const float* emb  = (const float*)d_in[2];
    const float* Wl   = (const float*)d_in[3];
    const float* bl   = (const float*)d_in[4];
    const float* Wr   = (const float*)d_in[5];
    const float* br   = (const float*)d_in[6];
    const float* att  = (const float*)d_in[7];
    const float* cb   = (const float*)d_in[8];
    const float* lng  = (const float*)d_in[9];
    const float* lnb  = (const float*)d_in[10];
    const float* linW = (const float*)d_in[11];
    const float* linb = (const float*)d_in[12];
    const float* bng  = (const float*)d_in[13];
    const float* bnb  = (const float*)d_in[14];
    float* out = (float*)d_out;

    float *p_h, *p_xg, *p_xl, *p_xr;
    uint32_t *p_Wph, *p_Wpl;
    cudaGetSymbolAddress((void**)&p_h,  g_h);
    cudaGetSymbolAddress((void**)&p_xg, g_xg);
    cudaGetSymbolAddress((void**)&p_xl, g_xl);
    cudaGetSymbolAddress((void**)&p_xr, g_xr);
    cudaGetSymbolAddress((void**)&p_Wph, g_Wph);
    cudaGetSymbolAddress((void**)&p_Wpl, g_Wpl);

    cudaFuncSetAttribute(gat_gemm<0,2>, cudaFuncAttributeMaxDynamicSharedMemorySize, SMEM_NB2);
    cudaFuncSetAttribute(gat_gemm<1,2>, cudaFuncAttributeMaxDynamicSharedMemorySize, SMEM_NB2);
    cudaFuncSetAttribute(gat_gemm<2,1>, cudaFuncAttributeMaxDynamicSharedMemorySize, SMEM_NB1);

    const int TPB = 256;
    zero_kernel<<<(N_ + TPB - 1) / TPB, TPB>>>();
    gather_kernel<<<(N_ * 32 + TPB - 1) / TPB, TPB>>>(x, emb);
    hist_kernel<<<(E2_ + TPB - 1) / TPB, TPB>>>(ei);
    scan1_kernel<<<30, 1024>>>();
    scan2_kernel<<<1, 32>>>();
    scan3_kernel<<<30, 1024>>>();
    scatter_kernel<<<(E2_ + TPB - 1) / TPB, TPB>>>(ei);
    pack_kernel<<<(13 * 8192 + 255) / 256, 256>>>(Wl, Wr, linW);

    const int GEMM_GRID = (N_ + 127) / 128;          // 235
    const int AGG_GRID  = (N_ * 32 + TPB - 1) / TPB; // warp per node

    for (int i = 0; i < L_; i++) {
        const float* Ain = (i == 0) ? p_h : p_xg;
        const uint32_t* WhL = p_Wph + (size_t)i * 8192;
        const uint32_t* WlL = p_Wpl + (size_t)i * 8192;
        const uint32_t* WhR = p_Wph + (size_t)(6 + i) * 8192;
        const uint32_t* WlR = p_Wpl + (size_t)(6 + i) * 8192;
        if (i == 0) {
            gat_gemm<0,2><<<GEMM_GRID, 256, SMEM_NB2>>>(
                Ain, nullptr, WhL, WlL, WhR, WlR, bl + i * D_, br + i * D_,
                p_xl, p_xr, nullptr, nullptr, 0);
        } else {
            gat_gemm<1,2><<<GEMM_GRID, 256, SMEM_NB2>>>(
                Ain, nullptr, WhL, WlL, WhR, WlR, bl + i * D_, br + i * D_,
                p_xl, p_xr, lng + (i - 1) * D_, lnb + (i - 1) * D_, i - 1);
        }
        if (i < L_ - 1)
            agg_kernel<1><<<AGG_GRID, 256>>>(att + i * D_, cb + i * D_, i);
        else
            agg_kernel<0><<<AGG_GRID, 256>>>(att + i * D_, cb + i * D_, 0);
    }

    gat_gemm<2,1><<<GEMM_GRID, 256, SMEM_NB1>>>(
        p_xg, p_h, p_Wph + (size_t)12 * 8192, p_Wpl + (size_t)12 * 8192,
        nullptr, nullptr, linb, nullptr,
        out, nullptr, nullptr, nullptr, 0);
    bnstats_kernel<<<256, D_>>>(out);
    bnnorm_kernel<<<(N_ * 32 + TPB - 1) / TPB, TPB>>>(out, bng, bnb);
}

// round 8
// speedup vs baseline: 1.3384x; 1.0274x over previous
#include <cuda_runtime.h>
#include <cuda_bf16.h>
#include <math.h>
#include <stdint.h>

// Problem constants
#define N_ 30000
#define D_ 128
#define E_ 240000
#define E2_ (E_ + N_)          // 270000
#define L_ 6
#define NEG_SLOPE 0.2f
#define EPS_ 1e-5f

// -------------------- device scratch --------------------
__device__ float g_h[N_ * D_];
__device__ float g_xg[N_ * D_];
__device__ float g_xl[N_ * D_];
__device__ float g_xr[N_ * D_];
// packed weights, [mat][kpair w 0..63][n 0..127]: bf16x2 along k, hi + lo residual
__device__ uint32_t g_Wph[13 * 8192];
__device__ uint32_t g_Wpl[13 * 8192];

__device__ int    g_deg[N_];
__device__ int    g_cursor[N_];
__device__ int    g_rowptr[N_ + 1];
__device__ int    g_srcs[E2_];
__device__ int    g_scanbuf[30720];
__device__ int    g_bsum[32];

__device__ double g_lnred[12];
__device__ float  g_bnsum[D_];
__device__ float  g_bnsq[D_];

// -------------------- helpers --------------------
__device__ __forceinline__ void mma_bf16(float* d, const uint32_t* a, const uint32_t* b) {
    asm volatile(
        "mma.sync.aligned.m16n8k16.row.col.f32.bf16.bf16.f32 "
        "{%0,%1,%2,%3}, {%4,%5,%6,%7}, {%8,%9}, {%0,%1,%2,%3};"
        : "+f"(d[0]), "+f"(d[1]), "+f"(d[2]), "+f"(d[3])
        : "r"(a[0]), "r"(a[1]), "r"(a[2]), "r"(a[3]), "r"(b[0]), "r"(b[1]));
}
__device__ __forceinline__ void split2(float x, float y, uint32_t& hi, uint32_t& lo) {
    __nv_bfloat16 hx = __float2bfloat16(x), hy = __float2bfloat16(y);
    float lx = x - __bfloat162float(hx);
    float ly = y - __bfloat162float(hy);
    __nv_bfloat16 lxh = __float2bfloat16(lx), lyh = __float2bfloat16(ly);
    hi = (uint32_t)__bfloat16_as_ushort(hx) | ((uint32_t)__bfloat16_as_ushort(hy) << 16);
    lo = (uint32_t)__bfloat16_as_ushort(lxh) | ((uint32_t)__bfloat16_as_ushort(lyh) << 16);
}
__device__ __forceinline__ float leaky(float v) { return v > 0.f ? v : NEG_SLOPE * v; }

// -------------------- small kernels --------------------
__global__ void zero_kernel() {
    int i = blockIdx.x * blockDim.x + threadIdx.x;
    if (i < N_) { g_deg[i] = 0; g_cursor[i] = 0; }
    if (i < 12) g_lnred[i] = 0.0;
    if (i < D_) { g_bnsum[i] = 0.f; g_bnsq[i] = 0.f; }
}

__global__ void gather_kernel(const int* __restrict__ x, const float* __restrict__ emb) {
    int i = blockIdx.x * blockDim.x + threadIdx.x;
    if (i >= N_ * 32) return;
    int n = i >> 5, c4 = i & 31;
    ((float4*)g_h)[i] = ((const float4*)(emb + (size_t)x[n] * D_))[c4];
}

__global__ void hist_kernel(const int* __restrict__ ei) {
    int e = blockIdx.x * blockDim.x + threadIdx.x;
    if (e >= E2_) return;
    int d = (e < E_) ? ei[E_ + e] : (e - E_);
    atomicAdd(&g_deg[d], 1);
}

__global__ void scan1_kernel() {
    __shared__ int sh[1024];
    int t = threadIdx.x, i = blockIdx.x * 1024 + t;
    int v = (i < N_) ? g_deg[i] : 0;
    sh[t] = v;
    __syncthreads();
    for (int o = 1; o < 1024; o <<= 1) {
        int u = (t >= o) ? sh[t - o] : 0;
        __syncthreads();
        sh[t] += u;
        __syncthreads();
    }
    g_scanbuf[i] = sh[t];
    if (t == 1023) g_bsum[blockIdx.x] = sh[1023];
}
__global__ void scan2_kernel() {
    int t = threadIdx.x;
    int orig = (t < 30) ? g_bsum[t] : 0;
    int v = orig;
    for (int o = 1; o < 32; o <<= 1) {
        int u = __shfl_up_sync(0xffffffffu, v, o);
        if (t >= o) v += u;
    }
    if (t < 30) g_bsum[t] = v - orig;
}
__global__ void scan3_kernel() {
    int t = threadIdx.x, i = blockIdx.x * 1024 + t;
    if (i > N_) return;
    int v = (i < N_) ? g_deg[i] : 0;
    g_rowptr[i] = g_bsum[blockIdx.x] + g_scanbuf[i] - v;
}

__global__ void scatter_kernel(const int* __restrict__ ei) {
    int e = blockIdx.x * blockDim.x + threadIdx.x;
    if (e >= E2_) return;
    int s, d;
    if (e < E_) { s = ei[e]; d = ei[E_ + e]; }
    else        { s = e - E_; d = s; }
    int pos = g_rowptr[d] + atomicAdd(&g_cursor[d], 1);
    g_srcs[pos] = s;
}

// pack weights: W[k][n] fp32 -> [w][n] bf16x2 hi/lo (w = k/2), 13 matrices
__global__ void pack_kernel(const float* __restrict__ Wl, const float* __restrict__ Wr,
                            const float* __restrict__ linW) {
    int idx = blockIdx.x * 256 + threadIdx.x;
    if (idx >= 13 * 8192) return;
    int mat = idx / 8192;
    int rem = idx - mat * 8192;
    int w = rem >> 7;
    int n = rem & 127;
    const float* src = (mat < 6) ? (Wl + mat * 16384)
                     : (mat < 12) ? (Wr + (mat - 6) * 16384) : linW;
    float v0 = src[(2 * w) * D_ + n];
    float v1 = src[(2 * w + 1) * D_ + n];
    uint32_t hi, lo;
    split2(v0, v1, hi, lo);
    g_Wph[mat * 8192 + w * 128 + n] = hi;
    g_Wpl[mat * 8192 + w * 128 + n] = lo;
}

// -------------------- bf16-split mma.sync GEMM, M=64 tiles, B via L1 --------
// PRE: 0 identity, 1 LN(graph)+ReLU, 2 A+resid.  NB: 1 or 2 weight matrices.
#define PW 68
#define TILEU (64 * PW)             // 4352 uints per array
#define GSMEM (2 * TILEU * 4)       // 34816 B (A hi + lo)

template<int PRE, int NB>
__global__ __launch_bounds__(256, 2) void gat_gemm(
    const float* __restrict__ A, const float* __restrict__ resid,
    const uint32_t* __restrict__ WhA, const uint32_t* __restrict__ WlA,
    const uint32_t* __restrict__ WhB, const uint32_t* __restrict__ WlB,
    const float* __restrict__ biasA, const float* __restrict__ biasB,
    float* __restrict__ CA, float* __restrict__ CB,
    const float* __restrict__ lnG, const float* __restrict__ lnB, int lnslot)
{
    extern __shared__ uint32_t smu[];
    uint32_t* Ah = smu;
    uint32_t* Al = smu + TILEU;

    const int tid = threadIdx.x, wid = tid >> 5, lane = tid & 31;
    const int row0 = blockIdx.x * 64;

    float mu = 0.f, inv = 0.f;
    if (PRE == 1) {
        double s  = g_lnred[lnslot * 2 + 0];
        double sq = g_lnred[lnslot * 2 + 1];
        const double cnt = (double)N_ * (double)D_;
        double m = s / cnt;
        mu  = (float)m;
        inv = (float)(1.0 / sqrt(sq / cnt - m * m + (double)EPS_));
    }

    // ---- stage A (pre-op + bf16 split): thread -> row tid>>2, quarter tid&3
    {
        const int r = tid >> 2, q = tid & 3;
        const bool aok = (row0 + r) < N_;
        const float* Arow = A + (size_t)(row0 + r) * D_;
        const float* Rrow = (PRE == 2) ? (resid + (size_t)(row0 + r) * D_) : nullptr;
#pragma unroll
        for (int i = 0; i < 8; i++) {
            int c4 = q * 8 + i;               // float4 index 0..31
            float4 v = make_float4(0.f, 0.f, 0.f, 0.f);
            if (aok) v = *(const float4*)(Arow + c4 * 4);
            if (PRE == 1) {
                float4 lg = *(const float4*)(lnG + c4 * 4);
                float4 lb = *(const float4*)(lnB + c4 * 4);
                v.x = fmaxf((v.x - mu) * inv * lg.x + lb.x, 0.f);
                v.y = fmaxf((v.y - mu) * inv * lg.y + lb.y, 0.f);
                v.z = fmaxf((v.z - mu) * inv * lg.z + lb.z, 0.f);
                v.w = fmaxf((v.w - mu) * inv * lg.w + lb.w, 0.f);
            } else if (PRE == 2) {
                if (aok) {
                    float4 rv = *(const float4*)(Rrow + c4 * 4);
                    v.x += rv.x; v.y += rv.y; v.z += rv.z; v.w += rv.w;
                }
            }
            uint32_t h0, l0, h1, l1;
            split2(v.x, v.y, h0, l0);
            split2(v.z, v.w, h1, l1);
            *(uint2*)&Ah[r * PW + c4 * 2] = make_uint2(h0, h1);
            *(uint2*)&Al[r * PW + c4 * 2] = make_uint2(l0, l1);
        }
    }
    __syncthreads();

    const int g  = lane >> 2;        // 0..7
    const int tg = lane & 3;         // 0..3
    const int wr = (wid >> 2) * 32;  // warp row slab (0/32)
    const int wc = (wid & 3) * 32;   // warp col slab

    float acc0[2][4][4], acc1[2][4][4];
#pragma unroll
    for (int mi = 0; mi < 2; mi++)
#pragma unroll
        for (int ni = 0; ni < 4; ni++)
#pragma unroll
            for (int j = 0; j < 4; j++) {
                acc0[mi][ni][j] = 0.f;
                if (NB == 2) acc1[mi][ni][j] = 0.f;
            }

    // B base offsets into [w][n] arrays for this lane
    const int bbase = tg * 128 + wc + g;   // w = tg, n = wc+g; +ni*8 along n; +k0*128 along w

#pragma unroll 2
    for (int ks = 0; ks < 8; ks++) {
        const int k0 = ks * 8;
        uint32_t ah[2][4], al[2][4];
#pragma unroll
        for (int mi = 0; mi < 2; mi++) {
            int o1 = (wr + mi * 16 + g) * PW + k0 + tg;
            int o2 = o1 + 8 * PW;
            ah[mi][0] = Ah[o1]; ah[mi][1] = Ah[o2];
            ah[mi][2] = Ah[o1 + 4]; ah[mi][3] = Ah[o2 + 4];
            al[mi][0] = Al[o1]; al[mi][1] = Al[o2];
            al[mi][2] = Al[o1 + 4]; al[mi][3] = Al[o2 + 4];
        }
        {
            uint32_t bh[4][2], bl[4][2];
            const int bo = k0 * 128 + bbase;
#pragma unroll
            for (int ni = 0; ni < 4; ni++) {
                bh[ni][0] = WhA[bo + ni * 8];
                bh[ni][1] = WhA[bo + 512 + ni * 8];
                bl[ni][0] = WlA[bo + ni * 8];
                bl[ni][1] = WlA[bo + 512 + ni * 8];
            }
#pragma unroll
            for (int mi = 0; mi < 2; mi++)
#pragma unroll
                for (int ni = 0; ni < 4; ni++)
                    mma_bf16(acc0[mi][ni], ah[mi], bh[ni]);
#pragma unroll
            for (int mi = 0; mi < 2; mi++)
#pragma unroll
                for (int ni = 0; ni < 4; ni++)
                    mma_bf16(acc0[mi][ni], ah[mi], bl[ni]);
#pragma unroll
            for (int mi = 0; mi < 2; mi++)
#pragma unroll
                for (int ni = 0; ni < 4; ni++)
                    mma_bf16(acc0[mi][ni], al[mi], bh[ni]);
        }
        if (NB == 2) {
            uint32_t bh[4][2], bl[4][2];
            const int bo = k0 * 128 + bbase;
#pragma unroll
            for (int ni = 0; ni < 4; ni++) {
                bh[ni][0] = WhB[bo + ni * 8];
                bh[ni][1] = WhB[bo + 512 + ni * 8];
                bl[ni][0] = WlB[bo + ni * 8];
                bl[ni][1] = WlB[bo + 512 + ni * 8];
            }
#pragma unroll
            for (int mi = 0; mi < 2; mi++)
#pragma unroll
                for (int ni = 0; ni < 4; ni++)
                    mma_bf16(acc1[mi][ni], ah[mi], bh[ni]);
#pragma unroll
            for (int mi = 0; mi < 2; mi++)
#pragma unroll
                for (int ni = 0; ni < 4; ni++)
                    mma_bf16(acc1[mi][ni], ah[mi], bl[ni]);
#pragma unroll
            for (int mi = 0; mi < 2; mi++)
#pragma unroll
                for (int ni = 0; ni < 4; ni++)
                    mma_bf16(acc1[mi][ni], al[mi], bh[ni]);
        }
    }

    // ---- epilogue ----
#pragma unroll
    for (int mat = 0; mat < NB; mat++) {
        const float* bias = mat ? biasB : biasA;
        float* C          = mat ? CB : CA;
#pragma unroll
        for (int mi = 0; mi < 2; mi++) {
            int r1 = row0 + wr + mi * 16 + g;
            int r2 = r1 + 8;
#pragma unroll
            for (int ni = 0; ni < 4; ni++) {
                float* a = mat ? acc1[mi][ni] : acc0[mi][ni];
                int col = wc + ni * 8 + tg * 2;
                float2 bv = *(const float2*)(bias + col);
                if (r1 < N_) {
                    float2 o = make_float2(a[0] + bv.x, a[1] + bv.y);
                    *(float2*)(C + (size_t)r1 * D_ + col) = o;
                }
                if (r2 < N_) {
                    float2 o = make_float2(a[2] + bv.x, a[3] + bv.y);
                    *(float2*)(C + (size_t)r2 * D_ + col) = o;
                }
            }
        }
    }
}

// -------------------- aggregation (warp per dst) + fused LN stats ----------
template<int STATS>
__global__ __launch_bounds__(256) void agg_kernel(
    const float* __restrict__ att, const float* __restrict__ cbias, int slot)
{
    __shared__ float ssum[8], ssq[8];
    int tid = threadIdx.x;
    int warp = (blockIdx.x * blockDim.x + tid) >> 5;
    int lane = tid & 31;
    int wid = tid >> 5;

    float4 o = make_float4(0.f, 0.f, 0.f, 0.f);
    if (warp < N_) {
        const float4 attv = ((const float4*)att)[lane];
        const float4 xrv  = ((const float4*)(g_xr + (size_t)warp * D_))[lane];
        int beg = g_rowptr[warp], end = g_rowptr[warp + 1];

        float m = -INFINITY, lsum = 0.f;
        float4 acc = make_float4(0.f, 0.f, 0.f, 0.f);
        for (int e = beg; e < end; e++) {
            int s = g_srcs[e];
            float4 v = ((const float4*)(g_xl + (size_t)s * D_))[lane];
            float p = leaky(v.x + xrv.x) * attv.x
                    + leaky(v.y + xrv.y) * attv.y
                    + leaky(v.z + xrv.z) * attv.z
                    + leaky(v.w + xrv.w) * attv.w;
#pragma unroll
            for (int of = 16; of > 0; of >>= 1)
                p += __shfl_xor_sync(0xffffffffu, p, of);
            float mn    = fmaxf(m, p);
            float scale = __expf(m - mn);
            float w     = __expf(p - mn);
            acc.x = acc.x * scale + w * v.x;
            acc.y = acc.y * scale + w * v.y;
            acc.z = acc.z * scale + w * v.z;
            acc.w = acc.w * scale + w * v.w;
            lsum  = lsum * scale + w;
            m = mn;
        }
        float invl = 1.f / lsum;
        float4 cb = ((const float4*)cbias)[lane];
        o = make_float4(acc.x * invl + cb.x, acc.y * invl + cb.y,
                        acc.z * invl + cb.z, acc.w * invl + cb.w);
        ((float4*)(g_xg + (size_t)warp * D_))[lane] = o;
    }

    if (STATS) {
        float s = o.x + o.y + o.z + o.w;
        float q = o.x * o.x + o.y * o.y + o.z * o.z + o.w * o.w;
#pragma unroll
        for (int of = 16; of > 0; of >>= 1) {
            s += __shfl_xor_sync(0xffffffffu, s, of);
            q += __shfl_xor_sync(0xffffffffu, q, of);
        }
        if (lane == 0) { ssum[wid] = s; ssq[wid] = q; }
        __syncthreads();
        if (tid == 0) {
            double S = 0.0, Q = 0.0;
#pragma unroll
            for (int i = 0; i < 8; i++) { S += (double)ssum[i]; Q += (double)ssq[i]; }
            atomicAdd(&g_lnred[slot * 2 + 0], S);
            atomicAdd(&g_lnred[slot * 2 + 1], Q);
        }
    }
}

// -------------------- BatchNorm --------------------
__global__ void bnstats_kernel(const float* __restrict__ out) {
    int c = threadIdx.x;
    float s = 0.f, q = 0.f;
    for (int r = blockIdx.x; r < N_; r += gridDim.x) {
        float v = out[(size_t)r * D_ + c];
        s += v; q += v * v;
    }
    atomicAdd(&g_bnsum[c], s);
    atomicAdd(&g_bnsq[c], q);
}

__global__ void bnnorm_kernel(float* __restrict__ out,
                              const float* __restrict__ bng,
                              const float* __restrict__ bnb) {
    int i = blockIdx.x * blockDim.x + threadIdx.x;
    if (i >= N_ * 32) return;
    int c4 = i & 31;
    float4 v  = ((float4*)out)[i];
    float4 su = ((const float4*)g_bnsum)[c4];
    float4 qu = ((const float4*)g_bnsq)[c4];
    float4 g  = ((const float4*)bng)[c4];
    float4 b  = ((const float4*)bnb)[c4];
    const float invN = 1.f / (float)N_;
    float mu, var;
    mu = su.x * invN; var = qu.x * invN - mu * mu;
    v.x = (v.x - mu) * rsqrtf(var + EPS_) * g.x + b.x;
    mu = su.y * invN; var = qu.y * invN - mu * mu;
    v.y = (v.y - mu) * rsqrtf(var + EPS_) * g.y + b.y;
    mu = su.z * invN; var = qu.z * invN - mu * mu;
    v.z = (v.z - mu) * rsqrtf(var + EPS_) * g.z + b.z;
    mu = su.w * invN; var = qu.w * invN - mu * mu;
    v.w = (v.w - mu) * rsqrtf(var + EPS_) * g.w + b.w;
    ((float4*)out)[i] = v;
}

// -------------------- launch --------------------
extern "C" void kernel_launch(void* const* d_in, const int* in_sizes, int n_in,
                              void* d_out, int out_size) {
    const int*   x    = (const int*)d_in[0];
    const int*   ei   = (const int*)d_in[1];
    const float* emb  = (const float*)d_in[2];
    const float* Wl   = (const float*)d_in[3];
    const float* bl   = (const float*)d_in[4];
    const float* Wr   = (const float*)d_in[5];
    const float* br   = (const float*)d_in[6];
    const float* att  = (const float*)d_in[7];
    const float* cb   = (const float*)d_in[8];
    const float* lng  = (const float*)d_in[9];
    const float* lnb  = (const float*)d_in[10];
    const float* linW = (const float*)d_in[11];
    const float* linb = (const float*)d_in[12];
    const float* bng  = (const float*)d_in[13];
    const float* bnb  = (const float*)d_in[14];
    float* out = (float*)d_out;

    float *p_h, *p_xg, *p_xl, *p_xr;
    uint32_t *p_Wph, *p_Wpl;
    cudaGetSymbolAddress((void**)&p_h,  g_h);
    cudaGetSymbolAddress((void**)&p_xg, g_xg);
    cudaGetSymbolAddress((void**)&p_xl, g_xl);
    cudaGetSymbolAddress((void**)&p_xr, g_xr);
    cudaGetSymbolAddress((void**)&p_Wph, g_Wph);
    cudaGetSymbolAddress((void**)&p_Wpl, g_Wpl);

    const int TPB = 256;
    zero_kernel<<<(N_ + TPB - 1) / TPB, TPB>>>();
    gather_kernel<<<(N_ * 32 + TPB - 1) / TPB, TPB>>>(x, emb);
    hist_kernel<<<(E2_ + TPB - 1) / TPB, TPB>>>(ei);
    scan1_kernel<<<30, 1024>>>();
    scan2_kernel<<<1, 32>>>();
    scan3_kernel<<<30, 1024>>>();
    scatter_kernel<<<(E2_ + TPB - 1) / TPB, TPB>>>(ei);
    pack_kernel<<<(13 * 8192 + 255) / 256, 256>>>(Wl, Wr, linW);

    const int GEMM_GRID = (N_ + 63) / 64;            // 469
    const int AGG_GRID  = (N_ * 32 + TPB - 1) / TPB; // warp per node

    for (int i = 0; i < L_; i++) {
        const float* Ain = (i == 0) ? p_h : p_xg;
        const uint32_t* WhL = p_Wph + (size_t)i * 8192;
        const uint32_t* WlL = p_Wpl + (size_t)i * 8192;
        const uint32_t* WhR = p_Wph + (size_t)(6 + i) * 8192;
        const uint32_t* WlR = p_Wpl + (size_t)(6 + i) * 8192;
        if (i == 0) {
            gat_gemm<0,2><<<GEMM_GRID, 256, GSMEM>>>(
                Ain, nullptr, WhL, WlL, WhR, WlR, bl + i * D_, br + i * D_,
                p_xl, p_xr, nullptr, nullptr, 0);
        } else {
            gat_gemm<1,2><<<GEMM_GRID, 256, GSMEM>>>(
                Ain, nullptr, WhL, WlL, WhR, WlR, bl + i * D_, br + i * D_,
                p_xl, p_xr, lng + (i - 1) * D_, lnb + (i - 1) * D_, i - 1);
        }
        if (i < L_ - 1)
            agg_kernel<1><<<AGG_GRID, 256>>>(att + i * D_, cb + i * D_, i);
        else
            agg_kernel<0><<<AGG_GRID, 256>>>(att + i * D_, cb + i * D_, 0);
    }

    gat_gemm<2,1><<<GEMM_GRID, 256, GSMEM>>>(
        p_xg, p_h, p_Wph + (size_t)12 * 8192, p_Wpl + (size_t)12 * 8192,
        nullptr, nullptr, linb, nullptr,
        out, nullptr, nullptr, nullptr, 0);
    bnstats_kernel<<<256, D_>>>(out);
    bnnorm_kernel<<<(N_ * 32 + TPB - 1) / TPB, TPB>>>(out, bng, bnb);
}